// round 2
// baseline (speedup 1.0000x reference)
#include <cuda_runtime.h>

#define NN 50000
#define NE 800000
#define F  128

// Scratch (device globals — no allocation allowed in kernel_launch)
__device__ float g_ptr [2][NN * F];   // x @ W.T per side
__device__ float g_acc [2][NN * F];   // unnormalized message accumulators
__device__ float g_norm[2][NN];       // per-node alpha sums
__device__ float g_asrc[2][NN];       // ptr @ head[:F]
__device__ float g_adst[2][NN];       // ptr @ head[F:]
__device__ int   g_i64mode;           // 1 if eidx is int64, 0 if int32

__device__ __forceinline__ void red_add_v4(float* addr, float a, float b, float c, float d) {
    asm volatile("red.global.add.v4.f32 [%0], {%1,%2,%3,%4};"
                 :: "l"(addr), "f"(a), "f"(b), "f"(c), "f"(d) : "memory");
}

// ---------------------------------------------------------------------------
// Detect eidx dtype. True int64 indices are all in [0, NN). int32 data read
// as int64 packs two indices per word -> values >= 2^32 (high word is the
// next, nonzero-with-prob~1 index). Checking 16 consecutive entries makes a
// false positive essentially impossible.
// ---------------------------------------------------------------------------
__global__ void detect_kernel(const void* eidx) {
    const long long* p = (const long long*)eidx;
    bool ok = true;
    #pragma unroll
    for (int i = 0; i < 16; ++i) {
        long long v = p[i];
        if (v < 0 || v >= NN) ok = false;
    }
    g_i64mode = ok ? 1 : 0;
}

// ---------------------------------------------------------------------------
// Zero the accumulators + norms (must re-zero every call; out is poisoned)
// ---------------------------------------------------------------------------
__global__ void zero_kernel() {
    const size_t n4_acc = (size_t)2 * NN * F / 4;   // 3.2M float4
    const size_t n4_nrm = (size_t)2 * NN / 4;       // 25k float4
    const size_t total  = n4_acc + n4_nrm;
    float4 z = make_float4(0.f, 0.f, 0.f, 0.f);
    float4* pa = (float4*)&g_acc[0][0];
    float4* pn = (float4*)&g_norm[0][0];
    for (size_t i = blockIdx.x * (size_t)blockDim.x + threadIdx.x; i < total;
         i += (size_t)gridDim.x * blockDim.x) {
        if (i < n4_acc) pa[i] = z;
        else            pn[i - n4_acc] = z;
    }
}

// ---------------------------------------------------------------------------
// GEMM: ptr[side] = x @ W.T   (M=NN, N=128, K=128)
// block = (32,8) = 256 threads, 128 rows x 128 cols per block.
// Thread (tx,ty): rows ty*16..ty*16+15, cols tx*4..tx*4+3 (float4 acc).
// Epilogue fuses a_src/a_dst = ptr @ head halves via warp shuffle reduction
// (a warp spans the full 128 output columns of each of its 16 rows).
// ---------------------------------------------------------------------------
__global__ __launch_bounds__(256, 2) void gemm_kernel(
    const float* __restrict__ x, const float* __restrict__ W,
    const float* __restrict__ head, int side)
{
    __shared__ float xs[32][F + 4];   // transposed: xs[k][m]
    __shared__ float ws[32][F + 4];   // transposed: ws[k][c] = W[c][k]

    const int tx = threadIdx.x;             // 0..31 (lane)
    const int ty = threadIdx.y;             // 0..7
    const int t  = ty * 32 + tx;
    const int row0 = blockIdx.x * 128;

    float4 acc[16];
    #pragma unroll
    for (int i = 0; i < 16; ++i) acc[i] = make_float4(0.f, 0.f, 0.f, 0.f);

    const int m  = t & 127;                 // row (for x) / col (for W) to load
    const int kg = (t >> 7) * 4;            // which group of 4 float4 k-columns
    const bool mvalid = (row0 + m) < NN;

    for (int kc = 0; kc < F; kc += 32) {
        __syncthreads();
        #pragma unroll
        for (int q = 0; q < 4; ++q) {
            int kq = kg + q;                // 0..7
            float4 v = make_float4(0.f, 0.f, 0.f, 0.f);
            if (mvalid) v = *(const float4*)&x[(size_t)(row0 + m) * F + kc + kq * 4];
            xs[kq * 4 + 0][m] = v.x; xs[kq * 4 + 1][m] = v.y;
            xs[kq * 4 + 2][m] = v.z; xs[kq * 4 + 3][m] = v.w;
            float4 wv = *(const float4*)&W[(size_t)m * F + kc + kq * 4];
            ws[kq * 4 + 0][m] = wv.x; ws[kq * 4 + 1][m] = wv.y;
            ws[kq * 4 + 2][m] = wv.z; ws[kq * 4 + 3][m] = wv.w;
        }
        __syncthreads();

        #pragma unroll
        for (int k = 0; k < 32; ++k) {
            float4 b = *(const float4*)&ws[k][tx * 4];
            #pragma unroll
            for (int g = 0; g < 4; ++g) {
                float4 a = *(const float4*)&xs[k][ty * 16 + g * 4];
                acc[g*4+0].x += a.x * b.x; acc[g*4+0].y += a.x * b.y;
                acc[g*4+0].z += a.x * b.z; acc[g*4+0].w += a.x * b.w;
                acc[g*4+1].x += a.y * b.x; acc[g*4+1].y += a.y * b.y;
                acc[g*4+1].z += a.y * b.z; acc[g*4+1].w += a.y * b.w;
                acc[g*4+2].x += a.z * b.x; acc[g*4+2].y += a.z * b.y;
                acc[g*4+2].z += a.z * b.z; acc[g*4+2].w += a.z * b.w;
                acc[g*4+3].x += a.w * b.x; acc[g*4+3].y += a.w * b.y;
                acc[g*4+3].z += a.w * b.z; acc[g*4+3].w += a.w * b.w;
            }
        }
    }

    // Epilogue: store ptr rows + fused head dot products
    float4 hs = *(const float4*)&head[tx * 4];
    float4 hd = *(const float4*)&head[F + tx * 4];
    #pragma unroll
    for (int i = 0; i < 16; ++i) {
        int r = row0 + ty * 16 + i;
        float4 v = acc[i];
        float ds = v.x * hs.x + v.y * hs.y + v.z * hs.z + v.w * hs.w;
        float dd = v.x * hd.x + v.y * hd.y + v.z * hd.z + v.w * hd.w;
        #pragma unroll
        for (int o = 16; o > 0; o >>= 1) {
            ds += __shfl_xor_sync(0xffffffffu, ds, o);
            dd += __shfl_xor_sync(0xffffffffu, dd, o);
        }
        if (r < NN) {
            *(float4*)&g_ptr[side][(size_t)r * F + tx * 4] = v;
            if (tx == 0) { g_asrc[side][r] = ds; g_adst[side][r] = dd; }
        }
    }
}

// ---------------------------------------------------------------------------
// Edge scatter: one warp per edge. Each edge belongs to exactly one side
// (esgn = +-1). Scatter UNNORMALIZED alpha * ptr[src] into g_acc[side][dst],
// and alpha into g_norm[side][dst]. Vector RED (sm_90+) for 4x fewer atomics.
// ---------------------------------------------------------------------------
__global__ __launch_bounds__(256) void edge_kernel(
    const void* __restrict__ eidx_raw, const float* __restrict__ ewt,
    const int* __restrict__ esgn)
{
    const int e    = blockIdx.x * 8 + (threadIdx.x >> 5);
    const int lane = threadIdx.x & 31;

    int s, t;
    if (g_i64mode) {
        const long long* eidx = (const long long*)eidx_raw;
        s = (int)eidx[e];
        t = (int)eidx[NE + e];
    } else {
        const int* eidx = (const int*)eidx_raw;
        s = eidx[e];
        t = eidx[NE + e];
    }
    const int side = (esgn[e] == 1) ? 0 : 1;

    float a = g_asrc[side][s] + g_adst[side][t];
    a = (a > 0.0f) ? a : 0.2f * a;                 // leaky_relu(0.2)
    const float al = __expf(a) * ewt[e];

    if (lane == 0) atomicAdd(&g_norm[side][t], al);

    float4 v = *(const float4*)&g_ptr[side][(size_t)s * F + lane * 4];
    red_add_v4(&g_acc[side][(size_t)t * F + lane * 4],
               v.x * al, v.y * al, v.z * al, v.w * al);
}

// ---------------------------------------------------------------------------
// Finalize: out[n] = accP[n]/normP' + accN[n]/normN'  (norm<=0 -> 1)
// ---------------------------------------------------------------------------
__global__ __launch_bounds__(256) void final_kernel(float* __restrict__ out) {
    const int i = blockIdx.x * blockDim.x + threadIdx.x;   // 0 .. NN*32-1
    const int n = i >> 5;
    const int q = i & 31;
    float np = g_norm[0][n]; np = (np > 0.f) ? np : 1.f;
    float nn = g_norm[1][n]; nn = (nn > 0.f) ? nn : 1.f;
    const float rp = 1.0f / np;
    const float rn = 1.0f / nn;
    float4 p = *(const float4*)&g_acc[0][(size_t)n * F + q * 4];
    float4 g = *(const float4*)&g_acc[1][(size_t)n * F + q * 4];
    float4 o = make_float4(p.x * rp + g.x * rn, p.y * rp + g.y * rn,
                           p.z * rp + g.z * rn, p.w * rp + g.w * rn);
    *(float4*)&out[(size_t)n * F + q * 4] = o;
}

// ---------------------------------------------------------------------------
extern "C" void kernel_launch(void* const* d_in, const int* in_sizes, int n_in,
                              void* d_out, int out_size) {
    const float* x    = (const float*)d_in[0];
    const void*  eidx = d_in[1];
    const float* ewt  = (const float*)d_in[2];
    const int*   esgn = (const int*)d_in[3];
    const float* Wp   = (const float*)d_in[4];
    const float* Wn   = (const float*)d_in[5];
    const float* hp   = (const float*)d_in[6];
    const float* hn   = (const float*)d_in[7];
    float* out = (float*)d_out;

    detect_kernel<<<1, 1>>>(eidx);
    zero_kernel<<<2048, 256>>>();

    dim3 gemm_block(32, 8);
    gemm_kernel<<<(NN + 127) / 128, gemm_block>>>(x, Wp, hp, 0);
    gemm_kernel<<<(NN + 127) / 128, gemm_block>>>(x, Wn, hn, 1);

    edge_kernel<<<NE / 8, 256>>>(eidx, ewt, esgn);

    final_kernel<<<(NN * F / 4) / 256, 256>>>(out);
}

// round 3
// speedup vs baseline: 1.4780x; 1.4780x over previous
#include <cuda_runtime.h>

#define NN 50000
#define NE 800000
#define F  128
#define NSEG (2 * NN)                 // (side, node) segments
#define SCAN_BLOCKS ((NSEG + 255) / 256)   // 391

// ---------------- device scratch (no allocations allowed) ----------------
__device__ float g_ptr [2][NN * F];   // x @ W.T per side
__device__ float g_asrc[2][NN];       // ptr @ head[:F]
__device__ float g_adst[2][NN];       // ptr @ head[F:]
__device__ int   g_cnt [NSEG];        // per (side,node) in-degree
__device__ int   g_off [NSEG];        // exclusive offsets
__device__ int   g_cur [NSEG];        // fill cursors
__device__ int   g_part[SCAN_BLOCKS]; // scan partials
__device__ int2  g_csr [NE];          // {src, __float_as_int(ewt)}
__device__ int   g_i64mode;

// ---------------------------------------------------------------------------
// Detect eidx dtype (int64 vs silently-downgraded int32).
// ---------------------------------------------------------------------------
__global__ void detect_kernel(const void* eidx) {
    const long long* p = (const long long*)eidx;
    bool ok = true;
    #pragma unroll
    for (int i = 0; i < 16; ++i) {
        long long v = p[i];
        if (v < 0 || v >= NN) ok = false;
    }
    g_i64mode = ok ? 1 : 0;
}

__device__ __forceinline__ int load_idx(const void* eidx, int pos) {
    if (g_i64mode) return (int)((const long long*)eidx)[pos];
    return ((const int*)eidx)[pos];
}

// ---------------------------------------------------------------------------
__global__ void zero_cnt_kernel() {
    int i = blockIdx.x * 256 + threadIdx.x;
    if (i < NSEG) g_cnt[i] = 0;
}

// ---------------------------------------------------------------------------
// GEMM: ptr[side] = x @ W.T, side = blockIdx.y. Fused head dot products.
// block (32,8); 128 rows x 128 cols per block; 16x4 register tile per thread.
// ---------------------------------------------------------------------------
__global__ __launch_bounds__(256, 2) void gemm_kernel(
    const float* __restrict__ x,
    const float* __restrict__ Wp, const float* __restrict__ Wn,
    const float* __restrict__ hp, const float* __restrict__ hn)
{
    __shared__ float xs[32][F + 4];   // xs[k][m]
    __shared__ float ws[32][F + 4];   // ws[k][c] = W[c][k]

    const int side = blockIdx.y;
    const float* __restrict__ W    = side ? Wn : Wp;
    const float* __restrict__ head = side ? hn : hp;

    const int tx = threadIdx.x;
    const int ty = threadIdx.y;
    const int t  = ty * 32 + tx;
    const int row0 = blockIdx.x * 128;

    float4 acc[16];
    #pragma unroll
    for (int i = 0; i < 16; ++i) acc[i] = make_float4(0.f, 0.f, 0.f, 0.f);

    const int m  = t & 127;
    const int kg = (t >> 7) * 4;
    const bool mvalid = (row0 + m) < NN;

    for (int kc = 0; kc < F; kc += 32) {
        __syncthreads();
        #pragma unroll
        for (int q = 0; q < 4; ++q) {
            int kq = kg + q;
            float4 v = make_float4(0.f, 0.f, 0.f, 0.f);
            if (mvalid) v = *(const float4*)&x[(size_t)(row0 + m) * F + kc + kq * 4];
            xs[kq * 4 + 0][m] = v.x; xs[kq * 4 + 1][m] = v.y;
            xs[kq * 4 + 2][m] = v.z; xs[kq * 4 + 3][m] = v.w;
            float4 wv = *(const float4*)&W[(size_t)m * F + kc + kq * 4];
            ws[kq * 4 + 0][m] = wv.x; ws[kq * 4 + 1][m] = wv.y;
            ws[kq * 4 + 2][m] = wv.z; ws[kq * 4 + 3][m] = wv.w;
        }
        __syncthreads();

        #pragma unroll
        for (int k = 0; k < 32; ++k) {
            float4 b = *(const float4*)&ws[k][tx * 4];
            #pragma unroll
            for (int g = 0; g < 4; ++g) {
                float4 a = *(const float4*)&xs[k][ty * 16 + g * 4];
                acc[g*4+0].x += a.x * b.x; acc[g*4+0].y += a.x * b.y;
                acc[g*4+0].z += a.x * b.z; acc[g*4+0].w += a.x * b.w;
                acc[g*4+1].x += a.y * b.x; acc[g*4+1].y += a.y * b.y;
                acc[g*4+1].z += a.y * b.z; acc[g*4+1].w += a.y * b.w;
                acc[g*4+2].x += a.z * b.x; acc[g*4+2].y += a.z * b.y;
                acc[g*4+2].z += a.z * b.z; acc[g*4+2].w += a.z * b.w;
                acc[g*4+3].x += a.w * b.x; acc[g*4+3].y += a.w * b.y;
                acc[g*4+3].z += a.w * b.z; acc[g*4+3].w += a.w * b.w;
            }
        }
    }

    float4 hs = *(const float4*)&head[tx * 4];
    float4 hd = *(const float4*)&head[F + tx * 4];
    #pragma unroll
    for (int i = 0; i < 16; ++i) {
        int r = row0 + ty * 16 + i;
        float4 v = acc[i];
        float ds = v.x * hs.x + v.y * hs.y + v.z * hs.z + v.w * hs.w;
        float dd = v.x * hd.x + v.y * hd.y + v.z * hd.z + v.w * hd.w;
        #pragma unroll
        for (int o = 16; o > 0; o >>= 1) {
            ds += __shfl_xor_sync(0xffffffffu, ds, o);
            dd += __shfl_xor_sync(0xffffffffu, dd, o);
        }
        if (r < NN) {
            *(float4*)&g_ptr[side][(size_t)r * F + tx * 4] = v;
            if (tx == 0) { g_asrc[side][r] = ds; g_adst[side][r] = dd; }
        }
    }
}

// ---------------------------------------------------------------------------
// Histogram of (side, target)
// ---------------------------------------------------------------------------
__global__ __launch_bounds__(256) void hist_kernel(const void* __restrict__ eidx,
                                                   const int* __restrict__ esgn) {
    int e = blockIdx.x * 256 + threadIdx.x;
    if (e >= NE) return;
    int t = load_idx(eidx, NE + e);
    int side = (esgn[e] == 1) ? 0 : 1;
    atomicAdd(&g_cnt[side * NN + t], 1);
}

// ---------------------------------------------------------------------------
// 3-kernel hierarchical exclusive scan of g_cnt -> g_off, g_cur
// ---------------------------------------------------------------------------
__global__ void scan1_kernel() {
    __shared__ int sh[256];
    int i = blockIdx.x * 256 + threadIdx.x;
    int v = (i < NSEG) ? g_cnt[i] : 0;
    sh[threadIdx.x] = v;
    __syncthreads();
    for (int o = 1; o < 256; o <<= 1) {
        int y = (threadIdx.x >= o) ? sh[threadIdx.x - o] : 0;
        __syncthreads();
        sh[threadIdx.x] += y;
        __syncthreads();
    }
    if (i < NSEG) g_off[i] = sh[threadIdx.x] - v;   // exclusive
    if (threadIdx.x == 255) g_part[blockIdx.x] = sh[255];
}

__global__ void scan2_kernel() {
    __shared__ int sh[512];
    int i = threadIdx.x;
    int v = (i < SCAN_BLOCKS) ? g_part[i] : 0;
    sh[i] = v;
    __syncthreads();
    for (int o = 1; o < 512; o <<= 1) {
        int y = (i >= o) ? sh[i - o] : 0;
        __syncthreads();
        sh[i] += y;
        __syncthreads();
    }
    if (i < SCAN_BLOCKS) g_part[i] = sh[i] - v;     // exclusive
}

__global__ void scan3_kernel() {
    int i = blockIdx.x * 256 + threadIdx.x;
    if (i < NSEG) {
        int o = g_off[i] + g_part[blockIdx.x];
        g_off[i] = o;
        g_cur[i] = o;
    }
}

// ---------------------------------------------------------------------------
// Fill CSR buckets: entry = {src, ewt}
// ---------------------------------------------------------------------------
__global__ __launch_bounds__(256) void fill_kernel(const void* __restrict__ eidx,
                                                   const float* __restrict__ ewt,
                                                   const int* __restrict__ esgn) {
    int e = blockIdx.x * 256 + threadIdx.x;
    if (e >= NE) return;
    int s = load_idx(eidx, e);
    int t = load_idx(eidx, NE + e);
    int side = (esgn[e] == 1) ? 0 : 1;
    int pos = atomicAdd(&g_cur[side * NN + t], 1);
    g_csr[pos] = make_int2(s, __float_as_int(ewt[e]));
}

// ---------------------------------------------------------------------------
// Gather: one warp per destination node; both sides; write output row once.
// out[t] = sum_side (Σ α ptr[s]) / max(Σ α, ->1)
// ---------------------------------------------------------------------------
__global__ __launch_bounds__(256) void gather_kernel(float* __restrict__ out) {
    const int warp = (blockIdx.x * 256 + threadIdx.x) >> 5;
    const int lane = threadIdx.x & 31;
    const int t = warp;
    if (t >= NN) return;

    float4 acc = make_float4(0.f, 0.f, 0.f, 0.f);

    #pragma unroll
    for (int side = 0; side < 2; ++side) {
        const int seg  = side * NN + t;
        const int base = g_off[seg];
        const int cnt  = g_cnt[seg];
        if (cnt == 0) continue;

        const float adst = g_adst[side][t];
        const float* __restrict__ ptr  = g_ptr[side];
        const float* __restrict__ asrc = g_asrc[side];

        float4 sacc = make_float4(0.f, 0.f, 0.f, 0.f);
        float  asum = 0.f;

        for (int c0 = 0; c0 < cnt; c0 += 32) {
            const int n = min(32, cnt - c0);
            int   s  = 0;
            float al = 0.f;
            if (lane < n) {
                int2 en = g_csr[base + c0 + lane];
                s = en.x;
                float a = asrc[s] + adst;
                a = (a > 0.f) ? a : 0.2f * a;          // leaky_relu(0.2)
                al = __expf(a) * __int_as_float(en.y);
            }
            // warp-sum of alphas
            float r = al;
            #pragma unroll
            for (int o = 16; o > 0; o >>= 1) r += __shfl_xor_sync(0xffffffffu, r, o);
            asum += r;
            // rank-1 accumulate: broadcast (s, alpha) per edge
            for (int i = 0; i < n; ++i) {
                int   si = __shfl_sync(0xffffffffu, s,  i);
                float ai = __shfl_sync(0xffffffffu, al, i);
                float4 v = *(const float4*)&ptr[(size_t)si * F + lane * 4];
                sacc.x += ai * v.x; sacc.y += ai * v.y;
                sacc.z += ai * v.z; sacc.w += ai * v.w;
            }
        }
        const float rnorm = (asum > 0.f) ? (1.0f / asum) : 1.0f;
        acc.x += sacc.x * rnorm; acc.y += sacc.y * rnorm;
        acc.z += sacc.z * rnorm; acc.w += sacc.w * rnorm;
    }

    *(float4*)&out[(size_t)t * F + lane * 4] = acc;
}

// ---------------------------------------------------------------------------
extern "C" void kernel_launch(void* const* d_in, const int* in_sizes, int n_in,
                              void* d_out, int out_size) {
    const float* x    = (const float*)d_in[0];
    const void*  eidx = d_in[1];
    const float* ewt  = (const float*)d_in[2];
    const int*   esgn = (const int*)d_in[3];
    const float* Wp   = (const float*)d_in[4];
    const float* Wn   = (const float*)d_in[5];
    const float* hp   = (const float*)d_in[6];
    const float* hn   = (const float*)d_in[7];
    float* out = (float*)d_out;

    detect_kernel<<<1, 1>>>(eidx);
    zero_cnt_kernel<<<SCAN_BLOCKS, 256>>>();

    gemm_kernel<<<dim3((NN + 127) / 128, 2), dim3(32, 8)>>>(x, Wp, Wn, hp, hn);

    hist_kernel<<<(NE + 255) / 256, 256>>>(eidx, esgn);
    scan1_kernel<<<SCAN_BLOCKS, 256>>>();
    scan2_kernel<<<1, 512>>>();
    scan3_kernel<<<SCAN_BLOCKS, 256>>>();
    fill_kernel<<<(NE + 255) / 256, 256>>>(eidx, ewt, esgn);

    gather_kernel<<<(NN * 32 + 255) / 256, 256>>>(out);
}

// round 4
// speedup vs baseline: 1.9716x; 1.3340x over previous
#include <cuda_runtime.h>
#include <cuda_bf16.h>
#include <cuda_fp16.h>

#define NN 50000
#define NE 800000
#define F  128
#define NSEG (2 * NN)
#define SCAN_BLOCKS ((NSEG + 255) / 256)   // 391
#define MTILES ((NN + 127) / 128)          // 391

// ---------------- device scratch ----------------
__device__ __half2 g_ptrh[2][(size_t)NN * 64];  // ptr rows as half2 (64 pairs)
__device__ float   g_asrc[2][NN];
__device__ float   g_adst[2][NN];
__device__ unsigned g_wpack[2][2][128 * 64];    // [side][hi/lo][n*64+pair] packed bf16x2
__device__ int   g_cnt [NSEG];
__device__ int   g_off [NSEG];
__device__ int   g_cur [NSEG];
__device__ int   g_part[SCAN_BLOCKS];
__device__ int2  g_csr [NE];
__device__ int   g_i64mode;

// ---------------------------------------------------------------------------
__global__ void detect_kernel(const void* eidx) {
    const long long* p = (const long long*)eidx;
    bool ok = true;
    #pragma unroll
    for (int i = 0; i < 16; ++i) {
        long long v = p[i];
        if (v < 0 || v >= NN) ok = false;
    }
    g_i64mode = ok ? 1 : 0;
}

__device__ __forceinline__ int load_idx(const void* eidx, int pos) {
    if (g_i64mode) return (int)((const long long*)eidx)[pos];
    return ((const int*)eidx)[pos];
}

__global__ void zero_cnt_kernel() {
    int i = blockIdx.x * 256 + threadIdx.x;
    if (i < NSEG) g_cnt[i] = 0;
}

// ---------------------------------------------------------------------------
// Split W into bf16 hi/lo packed pairs: g_wpack[side][0]=hi, [1]=lo.
// ---------------------------------------------------------------------------
__device__ __forceinline__ unsigned pack_hi(float a, float b) {
    __nv_bfloat16 ha = __float2bfloat16_rn(a), hb = __float2bfloat16_rn(b);
    return ((unsigned)__bfloat16_as_ushort(hb) << 16) | __bfloat16_as_ushort(ha);
}
__device__ __forceinline__ unsigned pack_lo(float a, float b) {
    float ra = a - __bfloat162float(__float2bfloat16_rn(a));
    float rb = b - __bfloat162float(__float2bfloat16_rn(b));
    return pack_hi(ra, rb);
}

__global__ void wprep_kernel(const float* __restrict__ Wp, const float* __restrict__ Wn) {
    int i = blockIdx.x * 256 + threadIdx.x;      // 0 .. 2*8192-1
    if (i >= 2 * 8192) return;
    int side = i >> 13;
    int j = i & 8191;                            // n*64 + pair
    const float* W = side ? Wn : Wp;
    float2 v = *(const float2*)&W[(j >> 6) * 128 + (j & 63) * 2];
    g_wpack[side][0][j] = pack_hi(v.x, v.y);
    g_wpack[side][1][j] = pack_lo(v.x, v.y);
}

// ---------------------------------------------------------------------------
// bf16x3 tensor-core GEMM: ptr = x @ W.T with segments
//   C = xh@whT + xl@whT + xh@wlT   (fp32 accumulate)
// CTA: 256 threads, tile 128 rows x 128 cols. Warp w: rows w*16..w*16+15.
// smem stride 68 words -> fragment loads are bank-conflict-free.
// ---------------------------------------------------------------------------
#define XS_H 0
#define XS_L (128 * 68)
#define WS_H (2 * 128 * 68)
#define WS_L (3 * 128 * 68)
#define SMEM_WORDS (4 * 128 * 68)

__device__ __forceinline__ void mma_bf16(float* c, const unsigned* a, unsigned b0, unsigned b1) {
    asm volatile(
        "mma.sync.aligned.m16n8k16.row.col.f32.bf16.bf16.f32 "
        "{%0,%1,%2,%3}, {%4,%5,%6,%7}, {%8,%9}, {%0,%1,%2,%3};"
        : "+f"(c[0]), "+f"(c[1]), "+f"(c[2]), "+f"(c[3])
        : "r"(a[0]), "r"(a[1]), "r"(a[2]), "r"(a[3]), "r"(b0), "r"(b1));
}

__global__ __launch_bounds__(256) void gemm_kernel(
    const float* __restrict__ x,
    const float* __restrict__ hp, const float* __restrict__ hn)
{
    extern __shared__ unsigned sm[];
    const int side = blockIdx.y;
    const int tid  = threadIdx.x;
    const int row0 = blockIdx.x * 128;

    // ---- load & convert x tile (128 rows x 64 pairs), copy W packs ----
    for (int i = tid; i < 8192; i += 256) {
        int row = i >> 6, p = i & 63;
        int gr = row0 + row;
        float2 v = make_float2(0.f, 0.f);
        if (gr < NN) v = *(const float2*)&x[(size_t)gr * F + p * 2];
        sm[XS_H + row * 68 + p] = pack_hi(v.x, v.y);
        sm[XS_L + row * 68 + p] = pack_lo(v.x, v.y);
        sm[WS_H + row * 68 + p] = g_wpack[side][0][i];
        sm[WS_L + row * 68 + p] = g_wpack[side][1][i];
    }
    __syncthreads();

    const int warp = tid >> 5;
    const int lane = tid & 31;
    const int g    = lane >> 2;      // groupID
    const int q    = lane & 3;       // thread-in-group
    const int rA   = warp * 16 + g;

    float c[16][4];
    #pragma unroll
    for (int n = 0; n < 16; ++n) { c[n][0]=0.f; c[n][1]=0.f; c[n][2]=0.f; c[n][3]=0.f; }

    unsigned a[8][4];
    #pragma unroll
    for (int seg = 0; seg < 3; ++seg) {
        const unsigned* A = sm + ((seg == 1) ? XS_L : XS_H);
        const unsigned* B = sm + ((seg == 2) ? WS_L : WS_H);
        #pragma unroll
        for (int ks = 0; ks < 8; ++ks) {
            a[ks][0] = A[(rA    ) * 68 + ks * 8 + q];
            a[ks][1] = A[(rA + 8) * 68 + ks * 8 + q];
            a[ks][2] = A[(rA    ) * 68 + ks * 8 + 4 + q];
            a[ks][3] = A[(rA + 8) * 68 + ks * 8 + 4 + q];
        }
        #pragma unroll
        for (int nt = 0; nt < 16; ++nt) {
            const unsigned* Bn = B + (nt * 8 + g) * 68;
            #pragma unroll
            for (int ks = 0; ks < 8; ++ks) {
                mma_bf16(c[nt], a[ks], Bn[ks * 8 + q], Bn[ks * 8 + 4 + q]);
            }
        }
    }

    // ---- epilogue: head dots + half2 stores ----
    const float* __restrict__ head = side ? hn : hp;
    float dsA = 0.f, ddA = 0.f, dsB = 0.f, ddB = 0.f;
    #pragma unroll
    for (int nt = 0; nt < 16; ++nt) {
        int col = nt * 8 + 2 * q;
        float h0 = __ldg(&head[col]),       h1 = __ldg(&head[col + 1]);
        float d0 = __ldg(&head[F + col]),   d1 = __ldg(&head[F + col + 1]);
        dsA += c[nt][0] * h0 + c[nt][1] * h1;
        ddA += c[nt][0] * d0 + c[nt][1] * d1;
        dsB += c[nt][2] * h0 + c[nt][3] * h1;
        ddB += c[nt][2] * d0 + c[nt][3] * d1;
    }
    #pragma unroll
    for (int o = 1; o <= 2; o <<= 1) {
        dsA += __shfl_xor_sync(0xffffffffu, dsA, o);
        ddA += __shfl_xor_sync(0xffffffffu, ddA, o);
        dsB += __shfl_xor_sync(0xffffffffu, dsB, o);
        ddB += __shfl_xor_sync(0xffffffffu, ddB, o);
    }

    const int grA = row0 + rA;
    const int grB = grA + 8;
    if (grA < NN) {
        #pragma unroll
        for (int nt = 0; nt < 16; ++nt)
            g_ptrh[side][(size_t)grA * 64 + nt * 4 + q] = __floats2half2_rn(c[nt][0], c[nt][1]);
        if (q == 0) { g_asrc[side][grA] = dsA; g_adst[side][grA] = ddA; }
    }
    if (grB < NN) {
        #pragma unroll
        for (int nt = 0; nt < 16; ++nt)
            g_ptrh[side][(size_t)grB * 64 + nt * 4 + q] = __floats2half2_rn(c[nt][2], c[nt][3]);
        if (q == 0) { g_asrc[side][grB] = dsB; g_adst[side][grB] = ddB; }
    }
}

// ---------------------------------------------------------------------------
// CSR build
// ---------------------------------------------------------------------------
__global__ __launch_bounds__(256) void hist_kernel(const void* __restrict__ eidx,
                                                   const int* __restrict__ esgn) {
    int e = blockIdx.x * 256 + threadIdx.x;
    if (e >= NE) return;
    int t = load_idx(eidx, NE + e);
    int side = (esgn[e] == 1) ? 0 : 1;
    atomicAdd(&g_cnt[side * NN + t], 1);
}

__global__ void scan1_kernel() {
    __shared__ int sh[256];
    int i = blockIdx.x * 256 + threadIdx.x;
    int v = (i < NSEG) ? g_cnt[i] : 0;
    sh[threadIdx.x] = v;
    __syncthreads();
    for (int o = 1; o < 256; o <<= 1) {
        int y = (threadIdx.x >= o) ? sh[threadIdx.x - o] : 0;
        __syncthreads();
        sh[threadIdx.x] += y;
        __syncthreads();
    }
    if (i < NSEG) g_off[i] = sh[threadIdx.x] - v;
    if (threadIdx.x == 255) g_part[blockIdx.x] = sh[255];
}

__global__ void scan2_kernel() {
    __shared__ int sh[512];
    int i = threadIdx.x;
    int v = (i < SCAN_BLOCKS) ? g_part[i] : 0;
    sh[i] = v;
    __syncthreads();
    for (int o = 1; o < 512; o <<= 1) {
        int y = (i >= o) ? sh[i - o] : 0;
        __syncthreads();
        sh[i] += y;
        __syncthreads();
    }
    if (i < SCAN_BLOCKS) g_part[i] = sh[i] - v;
}

__global__ void scan3_kernel() {
    int i = blockIdx.x * 256 + threadIdx.x;
    if (i < NSEG) {
        int o = g_off[i] + g_part[blockIdx.x];
        g_off[i] = o;
        g_cur[i] = o;
    }
}

__global__ __launch_bounds__(256) void fill_kernel(const void* __restrict__ eidx,
                                                   const float* __restrict__ ewt,
                                                   const int* __restrict__ esgn) {
    int e = blockIdx.x * 256 + threadIdx.x;
    if (e >= NE) return;
    int s = load_idx(eidx, e);
    int t = load_idx(eidx, NE + e);
    int side = (esgn[e] == 1) ? 0 : 1;
    int pos = atomicAdd(&g_cur[side * NN + t], 1);
    g_csr[pos] = make_int2(s, __float_as_int(ewt[e]));
}

// ---------------------------------------------------------------------------
// Gather: one warp per destination node, both sides, single output write.
// ---------------------------------------------------------------------------
__global__ __launch_bounds__(256) void gather_kernel(float* __restrict__ out) {
    const int t    = (blockIdx.x * 256 + threadIdx.x) >> 5;
    const int lane = threadIdx.x & 31;
    if (t >= NN) return;

    float4 acc = make_float4(0.f, 0.f, 0.f, 0.f);

    #pragma unroll
    for (int side = 0; side < 2; ++side) {
        const int seg  = side * NN + t;
        const int base = g_off[seg];
        const int cnt  = g_cnt[seg];
        if (cnt == 0) continue;

        const float adst = g_adst[side][t];
        const __half2* __restrict__ ptr = g_ptrh[side];
        const float* __restrict__ asrc  = g_asrc[side];

        float4 sacc = make_float4(0.f, 0.f, 0.f, 0.f);
        float  asum = 0.f;

        for (int c0 = 0; c0 < cnt; c0 += 32) {
            const int n = min(32, cnt - c0);
            int   s  = 0;
            float al = 0.f;
            if (lane < n) {
                int2 en = g_csr[base + c0 + lane];
                s = en.x;
                float a = asrc[s] + adst;
                a = (a > 0.f) ? a : 0.2f * a;
                al = __expf(a) * __int_as_float(en.y);
            }
            float r = al;
            #pragma unroll
            for (int o = 16; o > 0; o >>= 1) r += __shfl_xor_sync(0xffffffffu, r, o);
            asum += r;
            for (int i = 0; i < n; ++i) {
                int   si = __shfl_sync(0xffffffffu, s,  i);
                float ai = __shfl_sync(0xffffffffu, al, i);
                uint2 raw = *(const uint2*)&ptr[(size_t)si * 64 + lane * 2];
                float2 f0 = __half22float2(*(__half2*)&raw.x);
                float2 f1 = __half22float2(*(__half2*)&raw.y);
                sacc.x += ai * f0.x; sacc.y += ai * f0.y;
                sacc.z += ai * f1.x; sacc.w += ai * f1.y;
            }
        }
        const float rnorm = (asum > 0.f) ? (1.0f / asum) : 1.0f;
        acc.x += sacc.x * rnorm; acc.y += sacc.y * rnorm;
        acc.z += sacc.z * rnorm; acc.w += sacc.w * rnorm;
    }

    *(float4*)&out[(size_t)t * F + lane * 4] = acc;
}

// ---------------------------------------------------------------------------
extern "C" void kernel_launch(void* const* d_in, const int* in_sizes, int n_in,
                              void* d_out, int out_size) {
    const float* x    = (const float*)d_in[0];
    const void*  eidx = d_in[1];
    const float* ewt  = (const float*)d_in[2];
    const int*   esgn = (const int*)d_in[3];
    const float* Wp   = (const float*)d_in[4];
    const float* Wn   = (const float*)d_in[5];
    const float* hp   = (const float*)d_in[6];
    const float* hn   = (const float*)d_in[7];
    float* out = (float*)d_out;

    cudaFuncSetAttribute(gemm_kernel, cudaFuncAttributeMaxDynamicSharedMemorySize,
                         SMEM_WORDS * 4);

    detect_kernel<<<1, 1>>>(eidx);
    zero_cnt_kernel<<<SCAN_BLOCKS, 256>>>();
    wprep_kernel<<<(2 * 8192 + 255) / 256, 256>>>(Wp, Wn);

    gemm_kernel<<<dim3(MTILES, 2), 256, SMEM_WORDS * 4>>>(x, hp, hn);

    hist_kernel<<<(NE + 255) / 256, 256>>>(eidx, esgn);
    scan1_kernel<<<SCAN_BLOCKS, 256>>>();
    scan2_kernel<<<1, 512>>>();
    scan3_kernel<<<SCAN_BLOCKS, 256>>>();
    fill_kernel<<<(NE + 255) / 256, 256>>>(eidx, ewt, esgn);

    gather_kernel<<<(NN * 32 + 255) / 256, 256>>>(out);
}